// round 3
// baseline (speedup 1.0000x reference)
#include <cuda_runtime.h>
#include <cuda_bf16.h>
#include <cstdint>

#define B_DIM 4096
#define SPLIT 32
#define D_DIM 256
#define UNITS 256

#define MTILE 128
#define NTILE 256
#define KC 32
#define NSTAGE (D_DIM / KC)   // 8

// ---------------- smem layout ----------------
#define APITCH 80                       // bytes per 32-elem bf16 row (padded, conflict-free)
#define ABYTES (128 * APITCH)           // 10240 per term per buffer
#define BBYTES (256 * APITCH)           // 20480 per term per buffer
#define SM_A 0                          // (buf*2+term)*ABYTES -> 40960 total
#define SM_B 40960                      // (buf*2+term)*BBYTES -> 81920 total
#define SM_TOTAL (40960 + 81920)        // 122880

// pre-split W: layout [s][n][k] bf16 bits (k contiguous)
__device__ __align__(16) unsigned short g_Whi[SPLIT * UNITS * D_DIM];
__device__ __align__(16) unsigned short g_Wlo[SPLIT * UNITS * D_DIM];

// ---------------- helpers ----------------
__device__ __forceinline__ uint32_t smem_u32(const void* p) {
    uint32_t a;
    asm("{ .reg .u64 t; cvta.to.shared.u64 t, %1; cvt.u32.u64 %0, t; }" : "=r"(a) : "l"(p));
    return a;
}

#define STS128(addr, v) \
    asm volatile("st.shared.v4.b32 [%0], {%1,%2,%3,%4};" :: "r"(addr), "r"((v).x), "r"((v).y), "r"((v).z), "r"((v).w) : "memory")

__device__ __forceinline__ void cp16(uint32_t dst, const void* src) {
    asm volatile("cp.async.cg.shared.global [%0], [%1], 16;"
                 :: "r"(dst), "l"((unsigned long long)__cvta_generic_to_global(src)) : "memory");
}
#define CP_COMMIT() asm volatile("cp.async.commit_group;" ::: "memory")
#define CP_WAIT0()  asm volatile("cp.async.wait_group 0;" ::: "memory")

__device__ __forceinline__ void ldsm4(uint32_t* r, uint32_t addr) {
    asm volatile("ldmatrix.sync.aligned.m8n8.x4.shared.b16 {%0,%1,%2,%3}, [%4];"
                 : "=r"(r[0]), "=r"(r[1]), "=r"(r[2]), "=r"(r[3]) : "r"(addr));
}

__device__ __forceinline__ void mma_bf16(float* d, const uint32_t* a, const uint32_t* b) {
    asm volatile("mma.sync.aligned.m16n8k16.row.col.f32.bf16.bf16.f32 "
                 "{%0,%1,%2,%3}, {%4,%5,%6,%7}, {%8,%9}, {%0,%1,%2,%3};"
                 : "+f"(d[0]), "+f"(d[1]), "+f"(d[2]), "+f"(d[3])
                 : "r"(a[0]), "r"(a[1]), "r"(a[2]), "r"(a[3]), "r"(b[0]), "r"(b[1]));
}

// split 8 fp32 -> packed hi (truncate-to-bf16) and lo (round-to-bf16 of residual)
__device__ __forceinline__ void split8(const float4 a, const float4 c, uint4& hi, uint4& lo) {
    uint32_t ua[8] = { __float_as_uint(a.x), __float_as_uint(a.y), __float_as_uint(a.z), __float_as_uint(a.w),
                       __float_as_uint(c.x), __float_as_uint(c.y), __float_as_uint(c.z), __float_as_uint(c.w) };
    float    fa[8] = { a.x, a.y, a.z, a.w, c.x, c.y, c.z, c.w };
    uint32_t h[4], l[4];
#pragma unroll
    for (int i = 0; i < 4; i++) {
        h[i] = __byte_perm(ua[2 * i], ua[2 * i + 1], 0x7632);  // lo16 = bf16(f0), hi16 = bf16(f1)
        float r0 = fa[2 * i]     - __uint_as_float(ua[2 * i]     & 0xffff0000u);
        float r1 = fa[2 * i + 1] - __uint_as_float(ua[2 * i + 1] & 0xffff0000u);
        uint32_t lp;
        asm("cvt.rn.bf16x2.f32 %0, %1, %2;" : "=r"(lp) : "f"(r1), "f"(r0)); // d.lo = r0, d.hi = r1
        l[i] = lp;
    }
    hi = make_uint4(h[0], h[1], h[2], h[3]);
    lo = make_uint4(l[0], l[1], l[2], l[3]);
}

// ---------------- prep kernel: W[s][k][n] fp32 -> g_Whi/g_Wlo [s][n][k] bf16 ----------------
__global__ void prep_w_kernel(const float* __restrict__ W) {
    __shared__ float tile[32][33];
    int s = blockIdx.z;
    int kb = blockIdx.y * 32;
    int nb = blockIdx.x * 32;
    int tx = threadIdx.x, ty = threadIdx.y;
    const float* Ws = W + (size_t)s * D_DIM * UNITS;
#pragma unroll
    for (int i = 0; i < 4; i++) {
        int k = kb + ty + 8 * i;
        tile[ty + 8 * i][tx] = Ws[(size_t)k * UNITS + nb + tx];
    }
    __syncthreads();
#pragma unroll
    for (int i = 0; i < 4; i++) {
        int n = nb + ty + 8 * i;
        int k = kb + tx;
        float v = tile[tx][ty + 8 * i];
        uint32_t u = __float_as_uint(v);
        uint32_t uhi = u & 0xffff0000u;
        float lo = v - __uint_as_float(uhi);
        size_t idx = ((size_t)s * UNITS + n) * D_DIM + k;
        g_Whi[idx] = (unsigned short)(uhi >> 16);
        g_Wlo[idx] = __bfloat16_as_ushort(__float2bfloat16(lo));
    }
}

// ---------------- main GEMM kernel (HMMA, 3-term bf16 split, staggered staging) ----------------
__global__ void __launch_bounds__(256, 1) lc_hmma_kernel(
    const float* __restrict__ x, const float* __restrict__ bias, float* __restrict__ out) {
    extern __shared__ char smem[];
    uint32_t sb = smem_u32(smem);
    int tid = threadIdx.x;
    int wid = tid >> 5, lid = tid & 31;
    int mb = blockIdx.x;     // batch tile
    int s  = blockIdx.y;     // split
    int wm = wid >> 2;       // 0..1 : warp group (also m half)
    int wn = wid & 3;        // 0..3 : n quarter

    float acc[4][8][4];
#pragma unroll
    for (int i = 0; i < 4; i++)
#pragma unroll
        for (int j = 0; j < 8; j++)
#pragma unroll
            for (int v = 0; v < 4; v++) acc[i][j][v] = 0.f;

    // ---- staging role: group wm stages chunk (kc+1) when wm == (kc+1)&1 ----
    int l = tid & 127;   // local id within group (128 threads)

    // A staging: thread -> full row l (32 floats = 8 float4)
    const float* xrow = x + (((size_t)(mb * MTILE + l) * SPLIT + s) * D_DIM);
    uint32_t asts = sb + SM_A + (uint32_t)(l * APITCH);

    // B staging: thread -> n rows l and l+128, 4x16B per term per row
    const unsigned short* wh0 = g_Whi + ((size_t)s * UNITS + l) * D_DIM;
    const unsigned short* wl0 = g_Wlo + ((size_t)s * UNITS + l) * D_DIM;
    uint32_t bsts = sb + SM_B + (uint32_t)(l * APITCH);

    // ldmatrix lane offsets
    uint32_t a_off = (uint32_t)((wm * 64 + (lid & 7) + ((lid >> 3) & 1) * 8) * APITCH + (lid >> 4) * 16);
    uint32_t b_off = (uint32_t)((wn * 64 + (lid & 7) + ((lid >> 4) & 1) * 8) * APITCH + ((lid >> 3) & 1) * 16);

    float4 xa[8];

    // ---- prologue ----
    if (wm == 0) {
        // group0: stage chunk 0 into buf 0
#pragma unroll
        for (int j = 0; j < 8; j++) xa[j] = __ldg((const float4*)xrow + j);
#pragma unroll
        for (int h = 0; h < 2; h++) {
            uint4 hi0, lo0, hi1, lo1;
            split8(xa[4 * h + 0], xa[4 * h + 1], hi0, lo0);
            split8(xa[4 * h + 2], xa[4 * h + 3], hi1, lo1);
            STS128(asts + h * 32, hi0);          STS128(asts + h * 32 + 16, hi1);
            STS128(asts + ABYTES + h * 32, lo0); STS128(asts + ABYTES + h * 32 + 16, lo1);
        }
#pragma unroll
        for (int c = 0; c < 4; c++) {
            cp16(bsts + c * 16,                       wh0 + c * 8);
            cp16(bsts + BBYTES + c * 16,              wl0 + c * 8);
            cp16(bsts + 128 * APITCH + c * 16,          wh0 + (size_t)128 * D_DIM + c * 8);
            cp16(bsts + BBYTES + 128 * APITCH + c * 16, wl0 + (size_t)128 * D_DIM + c * 8);
        }
        CP_COMMIT();
        CP_WAIT0();
    } else {
        // group1: prefetch x regs for chunk 1 (it stages chunk 1 during kc=0)
#pragma unroll
        for (int j = 0; j < 8; j++) xa[j] = __ldg((const float4*)(xrow + KC) + j);
    }
    __syncthreads();

    // ---- main loop over 8 K-chunks ----
#pragma unroll 1
    for (int kc = 0; kc < NSTAGE; kc++) {
        int cur = kc & 1;
        int nxt = cur ^ 1;
        bool is_stager   = (wm == ((kc + 1) & 1)) && (kc < NSTAGE - 1);
        bool is_prefetch = (wm == (kc & 1)) && (kc < NSTAGE - 2);

        if (is_stager) {
            // issue B cp.async for chunk kc+1 first (max overlap)
            uint32_t bd = bsts + (uint32_t)(nxt * 2 * BBYTES);
            const unsigned short* wh = wh0 + (kc + 1) * KC;
            const unsigned short* wl = wl0 + (kc + 1) * KC;
#pragma unroll
            for (int c = 0; c < 4; c++) {
                cp16(bd + c * 16,                       wh + c * 8);
                cp16(bd + BBYTES + c * 16,              wl + c * 8);
                cp16(bd + 128 * APITCH + c * 16,          wh + (size_t)128 * D_DIM + c * 8);
                cp16(bd + BBYTES + 128 * APITCH + c * 16, wl + (size_t)128 * D_DIM + c * 8);
            }
            CP_COMMIT();
            // convert + STS A for chunk kc+1 (regs prefetched last chunk)
            uint32_t ad = asts + (uint32_t)(nxt * 2 * ABYTES);
#pragma unroll
            for (int h = 0; h < 2; h++) {
                uint4 hi0, lo0, hi1, lo1;
                split8(xa[4 * h + 0], xa[4 * h + 1], hi0, lo0);
                split8(xa[4 * h + 2], xa[4 * h + 3], hi1, lo1);
                STS128(ad + h * 32, hi0);          STS128(ad + h * 32 + 16, hi1);
                STS128(ad + ABYTES + h * 32, lo0); STS128(ad + ABYTES + h * 32 + 16, lo1);
            }
        } else if (is_prefetch) {
            // prefetch x regs for chunk kc+2 (this group stages it during kc+1)
#pragma unroll
            for (int j = 0; j < 8; j++) xa[j] = __ldg((const float4*)(xrow + (kc + 2) * KC) + j);
        }

        // ---- compute on buffer cur: K=32 -> 2 k16 steps, 3 terms ----
        uint32_t abase = sb + SM_A + (uint32_t)(cur * 2 * ABYTES) + a_off;
        uint32_t bbase = sb + SM_B + (uint32_t)(cur * 2 * BBYTES) + b_off;
#pragma unroll
        for (int ks = 0; ks < 2; ks++) {
            uint32_t ab = abase + ks * 32;
            uint32_t bb = bbase + ks * 32;
            uint32_t ah[16], bh[16], bl[16];
#pragma unroll
            for (int mf = 0; mf < 4; mf++) ldsm4(&ah[4 * mf], ab + mf * 16 * APITCH);
#pragma unroll
            for (int p = 0; p < 4; p++) ldsm4(&bh[4 * p], bb + p * 16 * APITCH);
            // term 1: xhi * whi
#pragma unroll
            for (int mf = 0; mf < 4; mf++)
#pragma unroll
                for (int nf = 0; nf < 8; nf++) mma_bf16(acc[mf][nf], &ah[4 * mf], &bh[2 * nf]);
            // term 2: xhi * wlo
#pragma unroll
            for (int p = 0; p < 4; p++) ldsm4(&bl[4 * p], bb + BBYTES + p * 16 * APITCH);
#pragma unroll
            for (int mf = 0; mf < 4; mf++)
#pragma unroll
                for (int nf = 0; nf < 8; nf++) mma_bf16(acc[mf][nf], &ah[4 * mf], &bl[2 * nf]);
            // term 3: xlo * whi (reuse ah regs for alo)
#pragma unroll
            for (int mf = 0; mf < 4; mf++) ldsm4(&ah[4 * mf], ab + ABYTES + mf * 16 * APITCH);
#pragma unroll
            for (int mf = 0; mf < 4; mf++)
#pragma unroll
                for (int nf = 0; nf < 8; nf++) mma_bf16(acc[mf][nf], &ah[4 * mf], &bh[2 * nf]);
        }

        if (is_stager) CP_WAIT0();
        if (kc < NSTAGE - 1) __syncthreads();
    }

    // ---- epilogue: bias + relu + store ----
    const float* brow = bias + s * UNITS;
#pragma unroll
    for (int mf = 0; mf < 4; mf++) {
        int r0 = mb * MTILE + wm * 64 + mf * 16 + (lid >> 2);
        float* o0 = out + ((size_t)r0 * SPLIT + s) * UNITS;
        float* o1 = o0 + (size_t)8 * SPLIT * UNITS;
#pragma unroll
        for (int nf = 0; nf < 8; nf++) {
            int c = wn * 64 + nf * 8 + 2 * (lid & 3);
            float2 bv = *(const float2*)(brow + c);
            float2 v0, v1;
            v0.x = fmaxf(acc[mf][nf][0] + bv.x, 0.f);
            v0.y = fmaxf(acc[mf][nf][1] + bv.y, 0.f);
            v1.x = fmaxf(acc[mf][nf][2] + bv.x, 0.f);
            v1.y = fmaxf(acc[mf][nf][3] + bv.y, 0.f);
            *(float2*)(o0 + c) = v0;
            *(float2*)(o1 + c) = v1;
        }
    }
}

// ---------------- launch ----------------
extern "C" void kernel_launch(void* const* d_in, const int* in_sizes, int n_in,
                              void* d_out, int out_size) {
    const float* x = (const float*)d_in[0];
    const float* W = (const float*)d_in[1];
    const float* b = (const float*)d_in[2];
    float* out = (float*)d_out;

    prep_w_kernel<<<dim3(8, 8, 32), dim3(32, 8)>>>(W);

    cudaFuncSetAttribute(lc_hmma_kernel, cudaFuncAttributeMaxDynamicSharedMemorySize, SM_TOTAL);
    lc_hmma_kernel<<<dim3(B_DIM / MTILE, SPLIT), 256, SM_TOTAL>>>(x, b, out);
}

// round 4
// speedup vs baseline: 1.2815x; 1.2815x over previous
#include <cuda_runtime.h>
#include <cuda_bf16.h>
#include <cstdint>

#define B_DIM 4096
#define SPLIT 32
#define D_DIM 256
#define UNITS 256

#define MTILE 128
#define NTILE 128
#define KC 32
#define NSTAGE (D_DIM / KC)   // 8

// ---------------- smem layout ----------------
#define APITCH 80                       // bytes per 32-elem bf16 row (padded, conflict-free)
#define ABYTES (128 * APITCH)           // 10240 per term per buffer
#define BBYTES (128 * APITCH)           // 10240 per term per buffer
#define SM_A 0                          // (buf*2+term)*ABYTES -> 40960 total
#define SM_B 40960                      // (buf*2+term)*BBYTES -> 40960 total
#define SM_TOTAL (40960 + 40960)        // 81920 -> 2 CTAs/SM

// pre-split W: layout [s][n][k] bf16 bits (k contiguous)
__device__ __align__(16) unsigned short g_Whi[SPLIT * UNITS * D_DIM];
__device__ __align__(16) unsigned short g_Wlo[SPLIT * UNITS * D_DIM];

// ---------------- helpers ----------------
__device__ __forceinline__ uint32_t smem_u32(const void* p) {
    uint32_t a;
    asm("{ .reg .u64 t; cvta.to.shared.u64 t, %1; cvt.u32.u64 %0, t; }" : "=r"(a) : "l"(p));
    return a;
}

#define STS128(addr, v) \
    asm volatile("st.shared.v4.b32 [%0], {%1,%2,%3,%4};" :: "r"(addr), "r"((v).x), "r"((v).y), "r"((v).z), "r"((v).w) : "memory")

__device__ __forceinline__ void cp16(uint32_t dst, const void* src) {
    asm volatile("cp.async.cg.shared.global [%0], [%1], 16;"
                 :: "r"(dst), "l"((unsigned long long)__cvta_generic_to_global(src)) : "memory");
}
#define CP_COMMIT() asm volatile("cp.async.commit_group;" ::: "memory")
#define CP_WAIT0()  asm volatile("cp.async.wait_group 0;" ::: "memory")

__device__ __forceinline__ void ldsm4(uint32_t* r, uint32_t addr) {
    asm volatile("ldmatrix.sync.aligned.m8n8.x4.shared.b16 {%0,%1,%2,%3}, [%4];"
                 : "=r"(r[0]), "=r"(r[1]), "=r"(r[2]), "=r"(r[3]) : "r"(addr));
}

__device__ __forceinline__ void mma_bf16(float* d, const uint32_t* a, const uint32_t* b) {
    asm volatile("mma.sync.aligned.m16n8k16.row.col.f32.bf16.bf16.f32 "
                 "{%0,%1,%2,%3}, {%4,%5,%6,%7}, {%8,%9}, {%0,%1,%2,%3};"
                 : "+f"(d[0]), "+f"(d[1]), "+f"(d[2]), "+f"(d[3])
                 : "r"(a[0]), "r"(a[1]), "r"(a[2]), "r"(a[3]), "r"(b[0]), "r"(b[1]));
}

// split 8 fp32 -> packed hi (truncate-to-bf16) and lo (round-to-bf16 of residual)
__device__ __forceinline__ void split8(const float4 a, const float4 c, uint4& hi, uint4& lo) {
    uint32_t ua[8] = { __float_as_uint(a.x), __float_as_uint(a.y), __float_as_uint(a.z), __float_as_uint(a.w),
                       __float_as_uint(c.x), __float_as_uint(c.y), __float_as_uint(c.z), __float_as_uint(c.w) };
    float    fa[8] = { a.x, a.y, a.z, a.w, c.x, c.y, c.z, c.w };
    uint32_t h[4], l[4];
#pragma unroll
    for (int i = 0; i < 4; i++) {
        h[i] = __byte_perm(ua[2 * i], ua[2 * i + 1], 0x7632);  // lo16 = bf16(f0), hi16 = bf16(f1)
        float r0 = fa[2 * i]     - __uint_as_float(ua[2 * i]     & 0xffff0000u);
        float r1 = fa[2 * i + 1] - __uint_as_float(ua[2 * i + 1] & 0xffff0000u);
        uint32_t lp;
        asm("cvt.rn.bf16x2.f32 %0, %1, %2;" : "=r"(lp) : "f"(r1), "f"(r0)); // d.lo = r0, d.hi = r1
        l[i] = lp;
    }
    hi = make_uint4(h[0], h[1], h[2], h[3]);
    lo = make_uint4(l[0], l[1], l[2], l[3]);
}

// ---------------- prep kernel: W[s][k][n] fp32 -> g_Whi/g_Wlo [s][n][k] bf16 ----------------
__global__ void prep_w_kernel(const float* __restrict__ W) {
    __shared__ float tile[32][33];
    int s = blockIdx.z;
    int kb = blockIdx.y * 32;
    int nb = blockIdx.x * 32;
    int tx = threadIdx.x, ty = threadIdx.y;
    const float* Ws = W + (size_t)s * D_DIM * UNITS;
#pragma unroll
    for (int i = 0; i < 4; i++) {
        int k = kb + ty + 8 * i;
        tile[ty + 8 * i][tx] = Ws[(size_t)k * UNITS + nb + tx];
    }
    __syncthreads();
#pragma unroll
    for (int i = 0; i < 4; i++) {
        int n = nb + ty + 8 * i;
        int k = kb + tx;
        float v = tile[tx][ty + 8 * i];
        uint32_t u = __float_as_uint(v);
        uint32_t uhi = u & 0xffff0000u;
        float lo = v - __uint_as_float(uhi);
        size_t idx = ((size_t)s * UNITS + n) * D_DIM + k;
        g_Whi[idx] = (unsigned short)(uhi >> 16);
        g_Wlo[idx] = __bfloat16_as_ushort(__float2bfloat16(lo));
    }
}

// ---------------- main GEMM kernel (HMMA, 3-term bf16 split, 2 CTAs/SM) ----------------
__global__ void __launch_bounds__(256, 2) lc_hmma_kernel(
    const float* __restrict__ x, const float* __restrict__ bias, float* __restrict__ out) {
    extern __shared__ char smem[];
    uint32_t sb = smem_u32(smem);
    int tid = threadIdx.x;
    int wid = tid >> 5, lid = tid & 31;
    int mb = blockIdx.x;     // batch tile (fastest -> W slice L2 reuse)
    int s  = blockIdx.y;     // split
    int nb = blockIdx.z;     // n half
    int wm = wid >> 2;       // 0..1 : m half (64 rows)
    int wn = wid & 3;        // 0..3 : n quarter (32 cols)

    float acc[4][4][4];
#pragma unroll
    for (int i = 0; i < 4; i++)
#pragma unroll
        for (int j = 0; j < 4; j++)
#pragma unroll
            for (int v = 0; v < 4; v++) acc[i][j][v] = 0.f;

    // A staging: thread -> (row, 16-float half)
    int arow = tid >> 1, ahalf = tid & 1;
    const float* xbase = x + (((size_t)(mb * MTILE + arow) * SPLIT + s) * D_DIM) + ahalf * 16;
    uint32_t asts = sb + SM_A + (uint32_t)(arow * APITCH + ahalf * 32);

    // B staging: thread -> (n-row, 16-elem half), 2 cp16 per term
    const unsigned short* whsrc = g_Whi + ((size_t)s * UNITS + nb * NTILE + arow) * D_DIM + ahalf * 16;
    const unsigned short* wlsrc = g_Wlo + ((size_t)s * UNITS + nb * NTILE + arow) * D_DIM + ahalf * 16;
    uint32_t bsts = sb + SM_B + (uint32_t)(arow * APITCH + ahalf * 32);

    // ldmatrix lane offsets
    uint32_t a_off = (uint32_t)((wm * 64 + (lid & 7) + ((lid >> 3) & 1) * 8) * APITCH + (lid >> 4) * 16);
    uint32_t b_off = (uint32_t)((wn * 32 + (lid & 7) + ((lid >> 4) & 1) * 8) * APITCH + ((lid >> 3) & 1) * 16);

    float4 xa[4];

    // ---- prologue: stage chunk 0 ----
#pragma unroll
    for (int j = 0; j < 4; j++) xa[j] = __ldg((const float4*)(xbase) + j);
    {
        uint4 h0, l0, h1, l1;
        split8(xa[0], xa[1], h0, l0);
        split8(xa[2], xa[3], h1, l1);
        STS128(asts, h0);          STS128(asts + 16, h1);
        STS128(asts + ABYTES, l0); STS128(asts + ABYTES + 16, l1);
    }
    cp16(bsts,               whsrc);
    cp16(bsts + 16,          whsrc + 8);
    cp16(bsts + BBYTES,      wlsrc);
    cp16(bsts + BBYTES + 16, wlsrc + 8);
    CP_COMMIT();
#pragma unroll
    for (int j = 0; j < 4; j++) xa[j] = __ldg((const float4*)(xbase + KC) + j);
    CP_WAIT0();
    __syncthreads();

    // ---- main loop over 8 K-chunks ----
#pragma unroll 1
    for (int kc = 0; kc < NSTAGE; kc++) {
        int cur = kc & 1;
        int nxt = cur ^ 1;

        if (kc < NSTAGE - 1) {
            uint32_t bd = bsts + (uint32_t)(nxt * 2 * BBYTES);
            const unsigned short* wh = whsrc + (kc + 1) * KC;
            const unsigned short* wl = wlsrc + (kc + 1) * KC;
            cp16(bd,               wh);
            cp16(bd + 16,          wh + 8);
            cp16(bd + BBYTES,      wl);
            cp16(bd + BBYTES + 16, wl + 8);
            CP_COMMIT();
            uint4 h0, l0, h1, l1;
            split8(xa[0], xa[1], h0, l0);
            split8(xa[2], xa[3], h1, l1);
            uint32_t ad = asts + (uint32_t)(nxt * 2 * ABYTES);
            STS128(ad, h0);          STS128(ad + 16, h1);
            STS128(ad + ABYTES, l0); STS128(ad + ABYTES + 16, l1);
        }
        if (kc < NSTAGE - 2) {
#pragma unroll
            for (int j = 0; j < 4; j++) xa[j] = __ldg((const float4*)(xbase + (kc + 2) * KC) + j);
        }

        // ---- compute on buffer cur: K=32 -> 2 k16 steps, 3 terms ----
        uint32_t abase = sb + SM_A + (uint32_t)(cur * 2 * ABYTES) + a_off;
        uint32_t bbase = sb + SM_B + (uint32_t)(cur * 2 * BBYTES) + b_off;
#pragma unroll
        for (int ks = 0; ks < 2; ks++) {
            uint32_t ab = abase + ks * 32;
            uint32_t bb = bbase + ks * 32;
            uint32_t ah[16], bh[8], bl[8];
#pragma unroll
            for (int mf = 0; mf < 4; mf++) ldsm4(&ah[4 * mf], ab + mf * 16 * APITCH);
#pragma unroll
            for (int p = 0; p < 2; p++) ldsm4(&bh[4 * p], bb + p * 16 * APITCH);
            // term 1: xhi * whi
#pragma unroll
            for (int mf = 0; mf < 4; mf++)
#pragma unroll
                for (int nf = 0; nf < 4; nf++) mma_bf16(acc[mf][nf], &ah[4 * mf], &bh[2 * nf]);
            // term 2: xhi * wlo
#pragma unroll
            for (int p = 0; p < 2; p++) ldsm4(&bl[4 * p], bb + BBYTES + p * 16 * APITCH);
#pragma unroll
            for (int mf = 0; mf < 4; mf++)
#pragma unroll
                for (int nf = 0; nf < 4; nf++) mma_bf16(acc[mf][nf], &ah[4 * mf], &bl[2 * nf]);
            // term 3: xlo * whi (reuse ah regs for alo)
#pragma unroll
            for (int mf = 0; mf < 4; mf++) ldsm4(&ah[4 * mf], ab + ABYTES + mf * 16 * APITCH);
#pragma unroll
            for (int mf = 0; mf < 4; mf++)
#pragma unroll
                for (int nf = 0; nf < 4; nf++) mma_bf16(acc[mf][nf], &ah[4 * mf], &bh[2 * nf]);
        }

        if (kc < NSTAGE - 1) {
            CP_WAIT0();
            __syncthreads();
        }
    }

    // ---- epilogue: bias + relu + store ----
    const float* brow = bias + s * UNITS + nb * NTILE;
#pragma unroll
    for (int mf = 0; mf < 4; mf++) {
        int r0 = mb * MTILE + wm * 64 + mf * 16 + (lid >> 2);
        float* o0 = out + ((size_t)r0 * SPLIT + s) * UNITS + nb * NTILE;
        float* o1 = o0 + (size_t)8 * SPLIT * UNITS;
#pragma unroll
        for (int nf = 0; nf < 4; nf++) {
            int c = wn * 32 + nf * 8 + 2 * (lid & 3);
            float2 bv = *(const float2*)(brow + c);
            float2 v0, v1;
            v0.x = fmaxf(acc[mf][nf][0] + bv.x, 0.f);
            v0.y = fmaxf(acc[mf][nf][1] + bv.y, 0.f);
            v1.x = fmaxf(acc[mf][nf][2] + bv.x, 0.f);
            v1.y = fmaxf(acc[mf][nf][3] + bv.y, 0.f);
            *(float2*)(o0 + c) = v0;
            *(float2*)(o1 + c) = v1;
        }
    }
}

// ---------------- launch ----------------
extern "C" void kernel_launch(void* const* d_in, const int* in_sizes, int n_in,
                              void* d_out, int out_size) {
    const float* x = (const float*)d_in[0];
    const float* W = (const float*)d_in[1];
    const float* b = (const float*)d_in[2];
    float* out = (float*)d_out;

    prep_w_kernel<<<dim3(8, 8, 32), dim3(32, 8)>>>(W);

    cudaFuncSetAttribute(lc_hmma_kernel, cudaFuncAttributeMaxDynamicSharedMemorySize, SM_TOTAL);
    lc_hmma_kernel<<<dim3(B_DIM / MTILE, SPLIT, UNITS / NTILE), 256, SM_TOTAL>>>(x, b, out);
}